// round 4
// baseline (speedup 1.0000x reference)
#include <cuda_runtime.h>

// Problem constants
#define Hn    128
#define Ln    512
#define Bn    128
#define NPTn  1023                 // 2L-1 nodes per tree
#define NTOT  (Bn * NPTn)          // 130944 nodes
#define NLEAF (Bn * Ln)            // 65536 leaves

// Persistent device state (no allocation allowed)
__device__ float g_h[NTOT * Hn];                 // 67 MB
__device__ float g_c[NTOT * Hn];                 // 67 MB
__device__ float g_scratch[NLEAF * 384];         // 100.7 MB; levels use stride 640 (32768*640 < this)

__device__ __forceinline__ float sigm(float x) { return 1.0f / (1.0f + expf(-x)); }

// ---------------------------------------------------------------------------
// Tiled fp32 GEMM, BM=BN=BK=64, 256 threads, 4x4 micro-tile per thread.
// ---------------------------------------------------------------------------
#define BM 64
#define BN 64
#define BK 64

// Leaf GEMM: scratch[r, 0:384] = emb[label[leaf_node(r)]] @ W_iou   (K = 128)
// grid (NLEAF/64, 6), block 256
__global__ __launch_bounds__(256) void leaf_gemm(const int* __restrict__ label,
                                                 const float* __restrict__ emb,
                                                 const float* __restrict__ W) {
    __shared__ float As[BM * BK];
    __shared__ float Bs[BK * BN];
    __shared__ int abase[BM];

    int tid  = threadIdx.x;
    int row0 = blockIdx.x * BM;
    int col0 = blockIdx.y * BN;

    if (tid < BM) {
        int r = row0 + tid;
        int g = (r >> 9) * NPTn + (r & 511);      // leaf j of tree t -> global node id
        abase[tid] = label[g] * Hn;
    }
    __syncthreads();

    int ty = tid >> 4, tx = tid & 15;
    float acc[4][4];
#pragma unroll
    for (int i = 0; i < 4; i++)
#pragma unroll
        for (int j = 0; j < 4; j++) acc[i][j] = 0.0f;

    for (int kk = 0; kk < Hn; kk += BK) {
#pragma unroll
        for (int it = 0; it < 4; it++) {
            int m = ty + 16 * it;
            float4 v = *(const float4*)(emb + abase[m] + kk + tx * 4);
            *(float4*)(As + m * BK + tx * 4) = v;
        }
#pragma unroll
        for (int it = 0; it < 4; it++) {
            int k = ty + 16 * it;
            float4 v = *(const float4*)(W + (kk + k) * 384 + col0 + tx * 4);
            *(float4*)(Bs + k * BN + tx * 4) = v;
        }
        __syncthreads();
#pragma unroll 8
        for (int k = 0; k < BK; k++) {
            float4 b = *(const float4*)(Bs + k * BN + tx * 4);
            float a0 = As[(ty * 4 + 0) * BK + k];
            float a1 = As[(ty * 4 + 1) * BK + k];
            float a2 = As[(ty * 4 + 2) * BK + k];
            float a3 = As[(ty * 4 + 3) * BK + k];
            acc[0][0] += a0 * b.x; acc[0][1] += a0 * b.y; acc[0][2] += a0 * b.z; acc[0][3] += a0 * b.w;
            acc[1][0] += a1 * b.x; acc[1][1] += a1 * b.y; acc[1][2] += a1 * b.z; acc[1][3] += a1 * b.w;
            acc[2][0] += a2 * b.x; acc[2][1] += a2 * b.y; acc[2][2] += a2 * b.z; acc[2][3] += a2 * b.w;
            acc[3][0] += a3 * b.x; acc[3][1] += a3 * b.y; acc[3][2] += a3 * b.z; acc[3][3] += a3 * b.w;
        }
        __syncthreads();
    }
#pragma unroll
    for (int i = 0; i < 4; i++) {
        int r = row0 + ty * 4 + i;
        *(float4*)(g_scratch + (size_t)r * 384 + col0 + tx * 4) =
            make_float4(acc[i][0], acc[i][1], acc[i][2], acc[i][3]);
    }
}

// Leaf apply: gates with c_in = 0. grid (NLEAF*128/256), block 256.
__global__ __launch_bounds__(256) void leaf_apply(const float* __restrict__ b_iou) {
    int idx = blockIdx.x * 256 + threadIdx.x;
    int r = idx >> 7, d = idx & 127;
    int node = (r >> 9) * NPTn + (r & 511);
    const float* s = g_scratch + (size_t)r * 384;
    float gi = s[d]       + b_iou[d];
    float go = s[128 + d] + b_iou[128 + d];
    float gu = s[256 + d] + b_iou[256 + d];
    float cc = sigm(gi) * tanhf(gu);
    g_c[node * Hn + d] = cc;
    g_h[node * Hn + d] = sigm(go) * tanhf(cc);
}

// Level GEMM: for n_d = 128*cnt internal nodes of one level,
// scratch[r, 0:256] = h_cat @ U_f_w ; scratch[r, 256:640] = h_cat @ U_iou
// h_cat row r = [h[left(r)] | h[right(r)]], K = 256, scratch stride 640.
// grid (n_d/64, 10), block 256
__global__ __launch_bounds__(256) void level_gemm(const float* __restrict__ Ufw,
                                                  const float* __restrict__ Uiou,
                                                  int shift, int choff) {
    __shared__ float As[BM * BK];
    __shared__ float Bs[BK * BN];
    __shared__ int lbase[BM];

    int tid  = threadIdx.x;
    int row0 = blockIdx.x * BM;
    int col0 = blockIdx.y * BN;

    if (tid < BM) {
        int r = row0 + tid;
        int t = r >> shift;
        int j = r & ((1 << shift) - 1);
        lbase[tid] = (t * NPTn + choff + 2 * j) * Hn;   // right = +Hn
    }
    __syncthreads();

    const float* Bptr;
    int ldb, bcol;
    if (col0 < 256) { Bptr = Ufw;  ldb = 256; bcol = col0; }
    else            { Bptr = Uiou; ldb = 384; bcol = col0 - 256; }

    int ty = tid >> 4, tx = tid & 15;
    float acc[4][4];
#pragma unroll
    for (int i = 0; i < 4; i++)
#pragma unroll
        for (int j = 0; j < 4; j++) acc[i][j] = 0.0f;

    for (int kk = 0; kk < 2 * Hn; kk += BK) {
        int koff = (kk < Hn) ? kk : (kk - Hn + Hn); // same value; select src below
#pragma unroll
        for (int it = 0; it < 4; it++) {
            int m = ty + 16 * it;
            int base = (kk < Hn) ? (lbase[m] + kk) : (lbase[m] + Hn + (kk - Hn));
            float4 v = *(const float4*)(g_h + base + tx * 4);
            *(float4*)(As + m * BK + tx * 4) = v;
        }
        (void)koff;
#pragma unroll
        for (int it = 0; it < 4; it++) {
            int k = ty + 16 * it;
            float4 v = *(const float4*)(Bptr + (kk + k) * ldb + bcol + tx * 4);
            *(float4*)(Bs + k * BN + tx * 4) = v;
        }
        __syncthreads();
#pragma unroll 8
        for (int k = 0; k < BK; k++) {
            float4 b = *(const float4*)(Bs + k * BN + tx * 4);
            float a0 = As[(ty * 4 + 0) * BK + k];
            float a1 = As[(ty * 4 + 1) * BK + k];
            float a2 = As[(ty * 4 + 2) * BK + k];
            float a3 = As[(ty * 4 + 3) * BK + k];
            acc[0][0] += a0 * b.x; acc[0][1] += a0 * b.y; acc[0][2] += a0 * b.z; acc[0][3] += a0 * b.w;
            acc[1][0] += a1 * b.x; acc[1][1] += a1 * b.y; acc[1][2] += a1 * b.z; acc[1][3] += a1 * b.w;
            acc[2][0] += a2 * b.x; acc[2][1] += a2 * b.y; acc[2][2] += a2 * b.z; acc[2][3] += a2 * b.w;
            acc[3][0] += a3 * b.x; acc[3][1] += a3 * b.y; acc[3][2] += a3 * b.z; acc[3][3] += a3 * b.w;
        }
        __syncthreads();
    }
#pragma unroll
    for (int i = 0; i < 4; i++) {
        int r = row0 + ty * 4 + i;
        *(float4*)(g_scratch + (size_t)r * 640 + col0 + tx * 4) =
            make_float4(acc[i][0], acc[i][1], acc[i][2], acc[i][3]);
    }
}

// Level apply: forget gates, child-sum cell, LSTM cell update.
// grid (n_d*128/256), block 256
__global__ __launch_bounds__(256) void level_apply(const float* __restrict__ b_iou,
                                                   const float* __restrict__ Ufb,
                                                   int shift, int off, int choff) {
    int idx = blockIdx.x * 256 + threadIdx.x;
    int r = idx >> 7, d = idx & 127;
    int t = r >> shift;
    int j = r & ((1 << shift) - 1);
    int tb = t * NPTn;
    int node = tb + off + j;
    int left = tb + choff + 2 * j;
    const float* s = g_scratch + (size_t)r * 640;
    float fl = sigm(s[d]       + Ufb[d]);
    float fr = sigm(s[128 + d] + Ufb[128 + d]);
    float cred = fl * g_c[left * Hn + d] + fr * g_c[(left + 1) * Hn + d];
    float gi = s[256 + d] + b_iou[d];
    float go = s[384 + d] + b_iou[128 + d];
    float gu = s[512 + d] + b_iou[256 + d];
    float cc = sigm(gi) * tanhf(gu) + cred;
    g_c[node * Hn + d] = cc;
    g_h[node * Hn + d] = sigm(go) * tanhf(cc);
}

// Root projection + log_softmax. grid 128 (trees), block 128 (out dims).
__global__ __launch_bounds__(128) void final_kernel(const float* __restrict__ W,
                                                    const float* __restrict__ b,
                                                    float* __restrict__ out) {
    __shared__ float hr[128];
    __shared__ float red[128];
    int t = blockIdx.x, o = threadIdx.x;
    hr[o] = g_h[(t * NPTn + NPTn - 1) * Hn + o];
    __syncthreads();
    float acc = b[o];
#pragma unroll 8
    for (int k = 0; k < 128; k++) acc += hr[k] * W[k * 128 + o];
    red[o] = acc;
    __syncthreads();
#pragma unroll
    for (int s = 64; s > 0; s >>= 1) {
        if (o < s) red[o] = fmaxf(red[o], red[o + s]);
        __syncthreads();
    }
    float mx = red[0];
    __syncthreads();
    red[o] = expf(acc - mx);
    __syncthreads();
#pragma unroll
    for (int s = 64; s > 0; s >>= 1) {
        if (o < s) red[o] += red[o + s];
        __syncthreads();
    }
    out[t * 128 + o] = acc - mx - logf(red[0]);
}

// ---------------------------------------------------------------------------
// Launch: leaves, then 9 topological levels (cnt = 256..1), then roots.
// Inputs (metadata order): label, emb, W_iou, U_iou, b_iou, U_f_w, U_f_b, W_out, b_out
// ---------------------------------------------------------------------------
extern "C" void kernel_launch(void* const* d_in, const int* in_sizes, int n_in,
                              void* d_out, int out_size) {
    const int*   label = (const int*)  d_in[0];
    const float* emb   = (const float*)d_in[1];
    const float* W_iou = (const float*)d_in[2];
    const float* U_iou = (const float*)d_in[3];
    const float* b_iou = (const float*)d_in[4];
    const float* U_f_w = (const float*)d_in[5];
    const float* U_f_b = (const float*)d_in[6];
    const float* W_out = (const float*)d_in[7];
    const float* b_out = (const float*)d_in[8];
    float* out = (float*)d_out;

    leaf_gemm<<<dim3(NLEAF / BM, 384 / BN), 256>>>(label, emb, W_iou);
    leaf_apply<<<(NLEAF * Hn) / 256, 256>>>(b_iou);

    for (int shift = 8; shift >= 0; shift--) {
        int cnt   = 1 << shift;                 // 256 .. 1
        int off   = NPTn - (2 * cnt - 1);
        int choff = NPTn - (4 * cnt - 1);
        int nd    = Bn * cnt;
        level_gemm<<<dim3(nd / BM, 640 / BN), 256>>>(U_f_w, U_iou, shift, choff);
        level_apply<<<(nd * Hn) / 256, 256>>>(b_iou, U_f_b, shift, off, choff);
    }

    final_kernel<<<Bn, 128>>>(W_out, b_out, out);
}